// round 1
// baseline (speedup 1.0000x reference)
#include <cuda_runtime.h>
#include <cstdint>

#define N_NODES 100000
#define N_EDGES 1600000
#define D 128          // D_IN == D_OUT == 128

// Scratch for support = x @ W + b  (allocation-free rule -> device global)
__device__ float g_support[(size_t)N_NODES * D];

// ---------------------------------------------------------------------------
// Zero-init of output (harness poisons d_out with 0xAA; atomics need zeros)
// ---------------------------------------------------------------------------
__global__ void zero_out_kernel(float4* __restrict__ out, int n4) {
    int i = blockIdx.x * blockDim.x + threadIdx.x;
    if (i < n4) out[i] = make_float4(0.f, 0.f, 0.f, 0.f);
}

// ---------------------------------------------------------------------------
// GEMM: support[r][c] = sum_k x[r][k] * W[k][c] + b[c]
// Block tile: 64 rows x 128 cols, KT=32. Thread tile: 8 rows x 4 cols,
// accumulated as packed f32x2 (fma.rn.f32x2 -> FFMA2, 2x fp32 throughput).
// ---------------------------------------------------------------------------
#define ROWS_PER_BLK 64
#define KT 32

__device__ __forceinline__ void fma_f32x2(unsigned long long& d,
                                          unsigned long long a,
                                          unsigned long long b) {
    asm("fma.rn.f32x2 %0, %1, %2, %0;" : "+l"(d) : "l"(a), "l"(b));
}

__device__ __forceinline__ unsigned long long pack_ff(float lo, float hi) {
    unsigned long long r;
    asm("mov.b64 %0, {%1, %2};" : "=l"(r) : "f"(lo), "f"(hi));
    return r;
}

__global__ __launch_bounds__(256, 2) void gemm_bias_kernel(
    const float* __restrict__ x, const float* __restrict__ W,
    const float* __restrict__ b, float* __restrict__ sup) {
    __shared__ float xs[ROWS_PER_BLK][KT + 1];  // +1 pad: conflict-free col reads
    __shared__ float ws[KT][D];

    const int tid  = threadIdx.x;
    const int row0 = blockIdx.x * ROWS_PER_BLK;
    const int cg   = tid & 31;   // lane -> 4-col group
    const int rg   = tid >> 5;   // warp -> 8-row group
    const int c0   = cg * 4;

    // accumulators: 8 rows x 2 f32x2 pairs, init with bias
    unsigned long long acc[8][2];
    {
        const unsigned long long b01 = pack_ff(b[c0], b[c0 + 1]);
        const unsigned long long b23 = pack_ff(b[c0 + 2], b[c0 + 3]);
#pragma unroll
        for (int i = 0; i < 8; i++) { acc[i][0] = b01; acc[i][1] = b23; }
    }

    for (int kt = 0; kt < D; kt += KT) {
        __syncthreads();
        // stage x tile: 64 rows x 32 k (8 elems/thread, coalesced 128B rows)
#pragma unroll
        for (int j = 0; j < 8; j++) {
            int idx = tid + j * 256;          // 0..2047
            int r = idx >> 5, k = idx & 31;
            int grow = row0 + r;
            xs[r][k] = (grow < N_NODES) ? x[(size_t)grow * D + kt + k] : 0.f;
        }
        // stage W tile: 32 k x 128 c as float4 (4/thread, coalesced)
#pragma unroll
        for (int j = 0; j < 4; j++) {
            int idx = tid + j * 256;          // float4 index 0..1023
            int k = idx >> 5, c4 = idx & 31;
            reinterpret_cast<float4*>(&ws[k][0])[c4] =
                reinterpret_cast<const float4*>(&W[(size_t)(kt + k) * D])[c4];
        }
        __syncthreads();

#pragma unroll
        for (int k = 0; k < KT; k++) {
            const unsigned long long w01 =
                *reinterpret_cast<const unsigned long long*>(&ws[k][c0]);
            const unsigned long long w23 =
                *reinterpret_cast<const unsigned long long*>(&ws[k][c0 + 2]);
#pragma unroll
            for (int i = 0; i < 8; i++) {
                float a = xs[rg * 8 + i][k];          // broadcast within warp
                unsigned long long aa = pack_ff(a, a);
                fma_f32x2(acc[i][0], aa, w01);
                fma_f32x2(acc[i][1], aa, w23);
            }
        }
    }

    // write 8 rows x 4 contiguous cols as float4
#pragma unroll
    for (int i = 0; i < 8; i++) {
        int grow = row0 + rg * 8 + i;
        if (grow < N_NODES) {
            float2 p01 = *reinterpret_cast<float2*>(&acc[i][0]);
            float2 p23 = *reinterpret_cast<float2*>(&acc[i][1]);
            float4 v = make_float4(p01.x, p01.y, p23.x, p23.y);
            *reinterpret_cast<float4*>(&sup[(size_t)grow * D + c0]) = v;
        }
    }
}

// ---------------------------------------------------------------------------
// Edge SpMM: out[rows[e]] += support[cols[e]] * vals[e]
// One warp per edge: lane handles one float4 (128B coalesced gather),
// scatter via scalar atomicAdd (REDG, no-return, spread addresses).
// ---------------------------------------------------------------------------
__global__ __launch_bounds__(256) void edge_spmm_kernel(
    const int* __restrict__ rows, const int* __restrict__ cols,
    const float* __restrict__ vals, const float* __restrict__ sup,
    float* __restrict__ out) {
    const int lane = threadIdx.x & 31;
    const int e = (blockIdx.x * blockDim.x + threadIdx.x) >> 5;
    if (e >= N_EDGES) return;

    const int r = __ldg(&rows[e]);
    const int c = __ldg(&cols[e]);
    const float v = __ldg(&vals[e]);

    const float4 s =
        reinterpret_cast<const float4*>(sup)[(size_t)c * (D / 4) + lane];
    float* o = out + (size_t)r * D + lane * 4;
    atomicAdd(o + 0, s.x * v);
    atomicAdd(o + 1, s.y * v);
    atomicAdd(o + 2, s.z * v);
    atomicAdd(o + 3, s.w * v);
}

// ---------------------------------------------------------------------------
// Launch
// Inputs (metadata order): x[f32 N*D], rows[i32 E], cols[i32 E], vals[f32 E],
//                          W[f32 D*D], b[f32 D].  Output: f32 N*D.
// ---------------------------------------------------------------------------
extern "C" void kernel_launch(void* const* d_in, const int* in_sizes, int n_in,
                              void* d_out, int out_size) {
    const float* x    = (const float*)d_in[0];
    const int*   rows = (const int*)d_in[1];
    const int*   cols = (const int*)d_in[2];
    const float* vals = (const float*)d_in[3];
    const float* W    = (const float*)d_in[4];
    const float* b    = (const float*)d_in[5];
    float* out = (float*)d_out;

    float* sup = nullptr;
    cudaGetSymbolAddress((void**)&sup, g_support);

    // 1) zero output (atomics + poison)
    {
        int n4 = (N_NODES * D) / 4;
        int blk = 256, grid = (n4 + blk - 1) / blk;
        zero_out_kernel<<<grid, blk>>>((float4*)out, n4);
    }
    // 2) support = x @ W + b
    {
        int grid = (N_NODES + ROWS_PER_BLK - 1) / ROWS_PER_BLK;
        gemm_bias_kernel<<<grid, 256>>>(x, W, b, sup);
    }
    // 3) out += A @ support (one warp per edge)
    {
        long long total_threads = (long long)N_EDGES * 32;
        int blk = 256;
        int grid = (int)((total_threads + blk - 1) / blk);
        edge_spmm_kernel<<<grid, blk>>>(rows, cols, vals, sup, out);
    }
}

// round 2
// speedup vs baseline: 1.0001x; 1.0001x over previous
#include <cuda_runtime.h>
#include <cstdint>

#define N_NODES 100000
#define N_EDGES 1600000
#define D 128          // D_IN == D_OUT == 128

// Scratch for support = x @ W + b  (allocation-free rule -> device global)
__device__ float g_support[(size_t)N_NODES * D];

// ---------------------------------------------------------------------------
// Zero-init of output (harness poisons d_out with 0xAA; atomics need zeros)
// ---------------------------------------------------------------------------
__global__ void zero_out_kernel(float4* __restrict__ out, int n4) {
    int i = blockIdx.x * blockDim.x + threadIdx.x;
    if (i < n4) out[i] = make_float4(0.f, 0.f, 0.f, 0.f);
}

// ---------------------------------------------------------------------------
// GEMM: support[r][c] = sum_k x[r][k] * W[k][c] + b[c]
// Block tile: 64 rows x 128 cols, KT=32. Thread tile: 8 rows x 4 cols,
// accumulated as packed f32x2 (fma.rn.f32x2 -> FFMA2, 2x fp32 throughput).
// ---------------------------------------------------------------------------
#define ROWS_PER_BLK 64
#define KT 32

__device__ __forceinline__ void fma_f32x2(unsigned long long& d,
                                          unsigned long long a,
                                          unsigned long long b) {
    asm("fma.rn.f32x2 %0, %1, %2, %0;" : "+l"(d) : "l"(a), "l"(b));
}

__device__ __forceinline__ unsigned long long pack_ff(float lo, float hi) {
    unsigned long long r;
    asm("mov.b64 %0, {%1, %2};" : "=l"(r) : "f"(lo), "f"(hi));
    return r;
}

__global__ __launch_bounds__(256, 2) void gemm_bias_kernel(
    const float* __restrict__ x, const float* __restrict__ W,
    const float* __restrict__ b, float* __restrict__ sup) {
    __shared__ float xs[ROWS_PER_BLK][KT + 1];  // +1 pad: conflict-free col reads
    __shared__ float ws[KT][D];

    const int tid  = threadIdx.x;
    const int row0 = blockIdx.x * ROWS_PER_BLK;
    const int cg   = tid & 31;   // lane -> 4-col group
    const int rg   = tid >> 5;   // warp -> 8-row group
    const int c0   = cg * 4;

    // accumulators: 8 rows x 2 f32x2 pairs, init with bias
    unsigned long long acc[8][2];
    {
        const unsigned long long b01 = pack_ff(b[c0], b[c0 + 1]);
        const unsigned long long b23 = pack_ff(b[c0 + 2], b[c0 + 3]);
#pragma unroll
        for (int i = 0; i < 8; i++) { acc[i][0] = b01; acc[i][1] = b23; }
    }

    for (int kt = 0; kt < D; kt += KT) {
        __syncthreads();
        // stage x tile: 64 rows x 32 k (8 elems/thread, coalesced 128B rows)
#pragma unroll
        for (int j = 0; j < 8; j++) {
            int idx = tid + j * 256;          // 0..2047
            int r = idx >> 5, k = idx & 31;
            int grow = row0 + r;
            xs[r][k] = (grow < N_NODES) ? x[(size_t)grow * D + kt + k] : 0.f;
        }
        // stage W tile: 32 k x 128 c as float4 (4/thread, coalesced)
#pragma unroll
        for (int j = 0; j < 4; j++) {
            int idx = tid + j * 256;          // float4 index 0..1023
            int k = idx >> 5, c4 = idx & 31;
            reinterpret_cast<float4*>(&ws[k][0])[c4] =
                reinterpret_cast<const float4*>(&W[(size_t)(kt + k) * D])[c4];
        }
        __syncthreads();

#pragma unroll
        for (int k = 0; k < KT; k++) {
            const unsigned long long w01 =
                *reinterpret_cast<const unsigned long long*>(&ws[k][c0]);
            const unsigned long long w23 =
                *reinterpret_cast<const unsigned long long*>(&ws[k][c0 + 2]);
#pragma unroll
            for (int i = 0; i < 8; i++) {
                float a = xs[rg * 8 + i][k];          // broadcast within warp
                unsigned long long aa = pack_ff(a, a);
                fma_f32x2(acc[i][0], aa, w01);
                fma_f32x2(acc[i][1], aa, w23);
            }
        }
    }

    // write 8 rows x 4 contiguous cols as float4
#pragma unroll
    for (int i = 0; i < 8; i++) {
        int grow = row0 + rg * 8 + i;
        if (grow < N_NODES) {
            float2 p01 = *reinterpret_cast<float2*>(&acc[i][0]);
            float2 p23 = *reinterpret_cast<float2*>(&acc[i][1]);
            float4 v = make_float4(p01.x, p01.y, p23.x, p23.y);
            *reinterpret_cast<float4*>(&sup[(size_t)grow * D + c0]) = v;
        }
    }
}

// ---------------------------------------------------------------------------
// Edge SpMM: out[rows[e]] += support[cols[e]] * vals[e]
// One warp per edge: lane handles one float4 (128B coalesced gather),
// scatter via scalar atomicAdd (REDG, no-return, spread addresses).
// ---------------------------------------------------------------------------
__global__ __launch_bounds__(256) void edge_spmm_kernel(
    const int* __restrict__ rows, const int* __restrict__ cols,
    const float* __restrict__ vals, const float* __restrict__ sup,
    float* __restrict__ out) {
    const int lane = threadIdx.x & 31;
    const int e = (blockIdx.x * blockDim.x + threadIdx.x) >> 5;
    if (e >= N_EDGES) return;

    const int r = __ldg(&rows[e]);
    const int c = __ldg(&cols[e]);
    const float v = __ldg(&vals[e]);

    const float4 s =
        reinterpret_cast<const float4*>(sup)[(size_t)c * (D / 4) + lane];
    float* o = out + (size_t)r * D + lane * 4;
    atomicAdd(o + 0, s.x * v);
    atomicAdd(o + 1, s.y * v);
    atomicAdd(o + 2, s.z * v);
    atomicAdd(o + 3, s.w * v);
}

// ---------------------------------------------------------------------------
// Launch
// Inputs (metadata order): x[f32 N*D], rows[i32 E], cols[i32 E], vals[f32 E],
//                          W[f32 D*D], b[f32 D].  Output: f32 N*D.
// ---------------------------------------------------------------------------
extern "C" void kernel_launch(void* const* d_in, const int* in_sizes, int n_in,
                              void* d_out, int out_size) {
    const float* x    = (const float*)d_in[0];
    const int*   rows = (const int*)d_in[1];
    const int*   cols = (const int*)d_in[2];
    const float* vals = (const float*)d_in[3];
    const float* W    = (const float*)d_in[4];
    const float* b    = (const float*)d_in[5];
    float* out = (float*)d_out;

    float* sup = nullptr;
    cudaGetSymbolAddress((void**)&sup, g_support);

    // 1) zero output (atomics + poison)
    {
        int n4 = (N_NODES * D) / 4;
        int blk = 256, grid = (n4 + blk - 1) / blk;
        zero_out_kernel<<<grid, blk>>>((float4*)out, n4);
    }
    // 2) support = x @ W + b
    {
        int grid = (N_NODES + ROWS_PER_BLK - 1) / ROWS_PER_BLK;
        gemm_bias_kernel<<<grid, 256>>>(x, W, b, sup);
    }
    // 3) out += A @ support (one warp per edge)
    {
        long long total_threads = (long long)N_EDGES * 32;
        int blk = 256;
        int grid = (int)((total_threads + blk - 1) / blk);
        edge_spmm_kernel<<<grid, blk>>>(rows, cols, vals, sup, out);
    }
}

// round 3
// speedup vs baseline: 2.8407x; 2.8405x over previous
#include <cuda_runtime.h>
#include <cstdint>

#define N_NODES 100000
#define N_EDGES 1600000
#define D 128          // D_IN == D_OUT == 128

#define SCAN_BLK 512
#define NB_SCAN ((N_NODES + SCAN_BLK - 1) / SCAN_BLK)   // 196

// ---- device-global scratch (allocation-free rule) ----
__device__ float g_support[(size_t)N_NODES * D];   // 51.2 MB
__device__ int   g_counts[N_NODES];
__device__ int   g_rowstart[N_NODES + 1];
__device__ int   g_cur[N_NODES];
__device__ int   g_sums[NB_SCAN];
__device__ int   g_offsets[NB_SCAN];
__device__ int   g_ccol[N_EDGES];                  // 6.4 MB
__device__ float g_cval[N_EDGES];                  // 6.4 MB

// ---------------------------------------------------------------------------
// 0) zero the per-row edge counters (must happen every call / graph replay)
// ---------------------------------------------------------------------------
__global__ void zero_counts_kernel() {
    int i = blockIdx.x * blockDim.x + threadIdx.x;
    if (i < N_NODES) g_counts[i] = 0;
}

// ---------------------------------------------------------------------------
// 1) GEMM: support[r][c] = sum_k x[r][k] * W[k][c] + b[c]   (f32x2 packed FMA)
// ---------------------------------------------------------------------------
#define ROWS_PER_BLK 64
#define KT 32

__device__ __forceinline__ void fma_f32x2(unsigned long long& d,
                                          unsigned long long a,
                                          unsigned long long b) {
    asm("fma.rn.f32x2 %0, %1, %2, %0;" : "+l"(d) : "l"(a), "l"(b));
}

__device__ __forceinline__ unsigned long long pack_ff(float lo, float hi) {
    unsigned long long r;
    asm("mov.b64 %0, {%1, %2};" : "=l"(r) : "f"(lo), "f"(hi));
    return r;
}

__global__ __launch_bounds__(256, 2) void gemm_bias_kernel(
    const float* __restrict__ x, const float* __restrict__ W,
    const float* __restrict__ b, float* __restrict__ sup) {
    __shared__ float xs[ROWS_PER_BLK][KT + 1];
    __shared__ float ws[KT][D];

    const int tid  = threadIdx.x;
    const int row0 = blockIdx.x * ROWS_PER_BLK;
    const int cg   = tid & 31;
    const int rg   = tid >> 5;
    const int c0   = cg * 4;

    unsigned long long acc[8][2];
    {
        const unsigned long long b01 = pack_ff(b[c0], b[c0 + 1]);
        const unsigned long long b23 = pack_ff(b[c0 + 2], b[c0 + 3]);
#pragma unroll
        for (int i = 0; i < 8; i++) { acc[i][0] = b01; acc[i][1] = b23; }
    }

    for (int kt = 0; kt < D; kt += KT) {
        __syncthreads();
#pragma unroll
        for (int j = 0; j < 8; j++) {
            int idx = tid + j * 256;
            int r = idx >> 5, k = idx & 31;
            int grow = row0 + r;
            xs[r][k] = (grow < N_NODES) ? x[(size_t)grow * D + kt + k] : 0.f;
        }
#pragma unroll
        for (int j = 0; j < 4; j++) {
            int idx = tid + j * 256;
            int k = idx >> 5, c4 = idx & 31;
            reinterpret_cast<float4*>(&ws[k][0])[c4] =
                reinterpret_cast<const float4*>(&W[(size_t)(kt + k) * D])[c4];
        }
        __syncthreads();

#pragma unroll
        for (int k = 0; k < KT; k++) {
            const unsigned long long w01 =
                *reinterpret_cast<const unsigned long long*>(&ws[k][c0]);
            const unsigned long long w23 =
                *reinterpret_cast<const unsigned long long*>(&ws[k][c0 + 2]);
#pragma unroll
            for (int i = 0; i < 8; i++) {
                float a = xs[rg * 8 + i][k];
                unsigned long long aa = pack_ff(a, a);
                fma_f32x2(acc[i][0], aa, w01);
                fma_f32x2(acc[i][1], aa, w23);
            }
        }
    }

#pragma unroll
    for (int i = 0; i < 8; i++) {
        int grow = row0 + rg * 8 + i;
        if (grow < N_NODES) {
            float2 p01 = *reinterpret_cast<float2*>(&acc[i][0]);
            float2 p23 = *reinterpret_cast<float2*>(&acc[i][1]);
            *reinterpret_cast<float4*>(&sup[(size_t)grow * D + c0]) =
                make_float4(p01.x, p01.y, p23.x, p23.y);
        }
    }
}

// ---------------------------------------------------------------------------
// 2) histogram of destination rows
// ---------------------------------------------------------------------------
__global__ void hist_kernel(const int* __restrict__ rows) {
    int e = blockIdx.x * blockDim.x + threadIdx.x;
    if (e < N_EDGES) atomicAdd(&g_counts[rows[e]], 1);
}

// ---------------------------------------------------------------------------
// 3a) per-block reduction of counts
// ---------------------------------------------------------------------------
__global__ void reduce_kernel() {
    __shared__ int sh[SCAN_BLK];
    int g = blockIdx.x * SCAN_BLK + threadIdx.x;
    sh[threadIdx.x] = (g < N_NODES) ? g_counts[g] : 0;
    __syncthreads();
#pragma unroll
    for (int s = SCAN_BLK / 2; s > 0; s >>= 1) {
        if (threadIdx.x < s) sh[threadIdx.x] += sh[threadIdx.x + s];
        __syncthreads();
    }
    if (threadIdx.x == 0) g_sums[blockIdx.x] = sh[0];
}

// 3b) exclusive scan of the 196 block sums (single block)
__global__ void scan_sums_kernel() {
    __shared__ int sh[NB_SCAN];
    int t = threadIdx.x;
    for (int i = t; i < NB_SCAN; i += blockDim.x) sh[i] = g_sums[i];
    __syncthreads();
    if (t == 0) {
        int run = 0;
        for (int i = 0; i < NB_SCAN; i++) { int v = sh[i]; sh[i] = run; run += v; }
    }
    __syncthreads();
    for (int i = t; i < NB_SCAN; i += blockDim.x) g_offsets[i] = sh[i];
}

// 3c) per-block exclusive scan + global offset -> row_start, cur
__global__ void scan_block_kernel() {
    __shared__ int sh[SCAN_BLK];
    int tid = threadIdx.x;
    int g = blockIdx.x * SCAN_BLK + tid;
    int v = (g < N_NODES) ? g_counts[g] : 0;
    sh[tid] = v;
    __syncthreads();
#pragma unroll
    for (int d = 1; d < SCAN_BLK; d <<= 1) {
        int t = (tid >= d) ? sh[tid - d] : 0;
        __syncthreads();
        sh[tid] += t;
        __syncthreads();
    }
    int incl = sh[tid];
    int excl = incl - v;
    int base = g_offsets[blockIdx.x];
    if (g < N_NODES) {
        int s = base + excl;
        g_rowstart[g] = s;
        g_cur[g] = s;
        if (g == N_NODES - 1) g_rowstart[N_NODES] = base + incl;
    }
}

// ---------------------------------------------------------------------------
// 4) scatter edges into CSR slots
// ---------------------------------------------------------------------------
__global__ void fill_kernel(const int* __restrict__ rows,
                            const int* __restrict__ cols,
                            const float* __restrict__ vals) {
    int e = blockIdx.x * blockDim.x + threadIdx.x;
    if (e < N_EDGES) {
        int r = rows[e];
        int pos = atomicAdd(&g_cur[r], 1);
        g_ccol[pos] = cols[e];
        g_cval[pos] = vals[e];
    }
}

// ---------------------------------------------------------------------------
// 5) SpMM: one warp per output row, gather-only, register accumulate,
//          single coalesced store (no atomics, no output zeroing needed).
// ---------------------------------------------------------------------------
__global__ __launch_bounds__(256) void spmm_kernel(float* __restrict__ out) {
    const int warp = (blockIdx.x * blockDim.x + threadIdx.x) >> 5;
    const int lane = threadIdx.x & 31;
    if (warp >= N_NODES) return;

    const int s = __ldg(&g_rowstart[warp]);
    const int e = __ldg(&g_rowstart[warp + 1]);

    const float4* sup4 = reinterpret_cast<const float4*>(g_support);
    float4 acc = make_float4(0.f, 0.f, 0.f, 0.f);

    int i = s;
    // 2 edges per iteration for MLP on the dependent gathers
    for (; i + 1 < e; i += 2) {
        int   c0 = __ldg(&g_ccol[i]);
        int   c1 = __ldg(&g_ccol[i + 1]);
        float v0 = __ldg(&g_cval[i]);
        float v1 = __ldg(&g_cval[i + 1]);
        float4 s0 = sup4[(size_t)c0 * (D / 4) + lane];
        float4 s1 = sup4[(size_t)c1 * (D / 4) + lane];
        acc.x += s0.x * v0; acc.y += s0.y * v0;
        acc.z += s0.z * v0; acc.w += s0.w * v0;
        acc.x += s1.x * v1; acc.y += s1.y * v1;
        acc.z += s1.z * v1; acc.w += s1.w * v1;
    }
    if (i < e) {
        int   c = __ldg(&g_ccol[i]);
        float v = __ldg(&g_cval[i]);
        float4 s0 = sup4[(size_t)c * (D / 4) + lane];
        acc.x += s0.x * v; acc.y += s0.y * v;
        acc.z += s0.z * v; acc.w += s0.w * v;
    }
    reinterpret_cast<float4*>(out)[(size_t)warp * (D / 4) + lane] = acc;
}

// ---------------------------------------------------------------------------
// Launch.  Inputs: x, rows, cols, vals, W, b.  Output: f32 [N_NODES, D].
// ---------------------------------------------------------------------------
extern "C" void kernel_launch(void* const* d_in, const int* in_sizes, int n_in,
                              void* d_out, int out_size) {
    const float* x    = (const float*)d_in[0];
    const int*   rows = (const int*)d_in[1];
    const int*   cols = (const int*)d_in[2];
    const float* vals = (const float*)d_in[3];
    const float* W    = (const float*)d_in[4];
    const float* b    = (const float*)d_in[5];
    float* out = (float*)d_out;

    float* sup = nullptr;
    cudaGetSymbolAddress((void**)&sup, g_support);

    // CSR build chain + GEMM (single stream; overlap is a next-round lever)
    zero_counts_kernel<<<(N_NODES + 255) / 256, 256>>>();

    gemm_bias_kernel<<<(N_NODES + ROWS_PER_BLK - 1) / ROWS_PER_BLK, 256>>>(
        x, W, b, sup);

    hist_kernel<<<(N_EDGES + 255) / 256, 256>>>(rows);
    reduce_kernel<<<NB_SCAN, SCAN_BLK>>>();
    scan_sums_kernel<<<1, 256>>>();
    scan_block_kernel<<<NB_SCAN, SCAN_BLK>>>();
    fill_kernel<<<(N_EDGES + 255) / 256, 256>>>(rows, cols, vals);

    // one warp per output row
    {
        long long total_threads = (long long)N_NODES * 32;
        int blk = 256;
        int grid = (int)((total_threads + blk - 1) / blk);
        spmm_kernel<<<grid, blk>>>(out);
    }
}